// round 12
// baseline (speedup 1.0000x reference)
#include <cuda_runtime.h>
#include <cstdint>

// Problem constants:
// B=32, N=32, P0=16, P1=32, P2=16, R=3, D=8, V=2
// num_in = 112, RD = 24
// out per b: 16 (null) + 1024 (unary) + 32*31*16 (binary) = 16912

#define RD 24
#define NUMIN 112

typedef unsigned long long u64;

// -------- device scratch --------
__device__ float g_BW[384 * 4];            // packed binary weights [kk][rdp]:(w0,w1,c0,c1)
__device__ float g_PU1T[32 * 32 * 24];     // [b][i][rd]  PN*U1*sigmoid(or)
__device__ float g_U2T[32 * 32 * 24];      // [b][j][rd]  U2
__device__ float g_partB[32 * 8];          // per (b, ig) partial nullary product
__device__ unsigned int g_ctr = 0;

// -------- packed f32x2 helpers (Blackwell) --------
__device__ __forceinline__ u64 pk2(float a, float b) {
    u64 r; asm("mov.b64 %0, {%1,%2};" : "=l"(r) : "f"(a), "f"(b)); return r;
}
__device__ __forceinline__ void upk2(u64 v, float& a, float& b) {
    asm("mov.b64 {%0,%1}, %2;" : "=f"(a), "=f"(b) : "l"(v));
}
__device__ __forceinline__ u64 fma2(u64 a, u64 b, u64 c) {
    u64 d; asm("fma.rn.f32x2 %0, %1, %2, %3;" : "=l"(d) : "l"(a), "l"(b), "l"(c)); return d;
}
__device__ __forceinline__ u64 mul2(u64 a, u64 b) {
    u64 d; asm("mul.rn.f32x2 %0, %1, %2;" : "=l"(d) : "l"(a), "l"(b)); return d;
}
__device__ __forceinline__ void lds_wc(u64& w, u64& c, uint32_t addr) {
    asm volatile("ld.shared.v2.u64 {%0,%1}, [%2];" : "=l"(w), "=l"(c) : "r"(addr));
}
__device__ __forceinline__ uint32_t smem_u32(const void* p) {
    uint32_t a;
    asm("{ .reg .u64 t; cvta.to.shared.u64 t, %1; cvt.u32.u64 %0, t; }" : "=r"(a) : "l"(p));
    return a;
}

// ============================================================================
// k1: weights + per-(b,obj) partial products (R7 version, verified).
// grid = (32 b, 2 h), block = 384. Each block handles rd in [h*12, h*12+12).
// ============================================================================
__global__ __launch_bounds__(384, 1)
void k1(const float* __restrict__ nul, const float* __restrict__ una,
        const float* __restrict__ andk, const float* __restrict__ ork) {
    __shared__ float2 sWC[12 * NUMIN];
    __shared__ float  sU[32 * 32];
    __shared__ float  sN[16];
    __shared__ float  sOK[12];

    const int b = blockIdx.x;
    const int h = blockIdx.y;
    const int t = threadIdx.x;

    for (int l = t; l < 12 * NUMIN; l += 384) {
        int gidx = h * (12 * NUMIN) + l;
        float a0 = andk[gidx * 3 + 0];
        float a1 = andk[gidx * 3 + 1];
        float a2 = andk[gidx * 3 + 2];
        float e0 = __expf(a0), e1 = __expf(a1), e2 = __expf(a2);
        float inv = __fdividef(1.0f, e0 + e1 + e2);
        sWC[l] = make_float2((e0 - e1) * inv, (e1 + e2) * inv);
    }
    for (int idx = t; idx < 1024; idx += 384) {
        int ii = idx >> 5, k = idx & 31;
        sU[k * 32 + ii] = una[b * 1024 + idx];
    }
    if (t < 16) sN[t] = nul[b * 16 + t];
    else if (t >= 32 && t < 44) {
        float x = ork[h * 12 + (t - 32)];
        sOK[t - 32] = __fdividef(1.0f, 1.0f + __expf(-x));
    }
    __syncthreads();

    if (b == 0 && t < 192) {
        int kk = t / 6, rdpl = t % 6;
        int slice = (kk < 16) ? (80 + kk) : (96 + kk - 16);
        float2 lo = sWC[(2 * rdpl)     * NUMIN + slice];
        float2 hi = sWC[(2 * rdpl + 1) * NUMIN + slice];
        ((float4*)g_BW)[kk * 12 + h * 6 + rdpl] = make_float4(lo.x, hi.x, lo.y, hi.y);
    }

    const int obj = t & 31;
    const int rdl = t >> 5;
    const int rd  = h * 12 + rdl;

    {
        const float2* wc = sWC + rdl * NUMIN + 48;
        float pa = 1.0f, pb = 1.0f, pc = 1.0f, pd = 1.0f;
#pragma unroll
        for (int k = 0; k < 8; k++) {
            float2 w0 = wc[k],      w1 = wc[8 + k];
            float2 w2 = wc[16 + k], w3 = wc[24 + k];
            pa *= fmaf(sU[k * 32 + obj],        w0.x, w0.y);
            pb *= fmaf(sU[(8 + k) * 32 + obj],  w1.x, w1.y);
            pc *= fmaf(sU[(16 + k) * 32 + obj], w2.x, w2.y);
            pd *= fmaf(sU[(24 + k) * 32 + obj], w3.x, w3.y);
        }
        g_U2T[(b * 32 + obj) * 24 + rd] = (pa * pb) * (pc * pd);
    }
    {
        const float2* wc = sWC + rdl * NUMIN;
        float pa = 1.0f, pb = 1.0f, pc = 1.0f, pd = 1.0f;
#pragma unroll
        for (int k = 0; k < 8; k++) {
            float2 w0 = wc[k], w1 = wc[8 + k];
            pa *= fmaf(sN[k],     w0.x, w0.y);
            pb *= fmaf(sN[8 + k], w1.x, w1.y);
        }
#pragma unroll
        for (int k = 0; k < 16; k++) {
            float2 w0 = wc[16 + k], w1 = wc[32 + k];
            pc *= fmaf(sU[k * 32 + obj],        w0.x, w0.y);
            pd *= fmaf(sU[(16 + k) * 32 + obj], w1.x, w1.y);
        }
        g_PU1T[(b * 32 + obj) * 24 + rd] = ((pa * pb) * (pc * pd)) * sOK[rdl];
    }
}

// ============================================================================
// k2: hot kernel. grid = (8 ig, 32 b), block = 256 = 8 warps.
// wid: half = wid>>2 (0: kk 0..15 + epilogue, 1: kk 16..31), i_loc = wid&3.
// Pure-load prologue; sAcc slab reused for coalesced xs load + out staging.
// ============================================================================
__global__ __launch_bounds__(256, 2)
void k2(const float* __restrict__ nul, const float* __restrict__ una,
        const float* __restrict__ binp, float* __restrict__ out) {
    __shared__ float4 sBW[384];            // packed binary weights [kk][rdp]
    __shared__ float  sU2[32 * 25];        // U2[j][rd]
    __shared__ float  sPU1[4 * 24];        // PU1 for local 4 i's
    __shared__ __align__(16) u64 sAcc[4 * 384];  // 4 slabs x 3072 B
    __shared__ float  sWarpR0[4];
    __shared__ int    sIsLast;

    const int ig   = blockIdx.x;           // 0..7
    const int b    = blockIdx.y;           // 0..31
    const int t    = threadIdx.x;          // 0..255
    const int wid  = t >> 5;               // 0..7
    const int lane = t & 31;
    const int half  = wid >> 2;            // 0 or 1
    const int i_loc = wid & 3;
    const int i     = ig * 4 + i_loc;

    const int  jj     = lane;
    const bool active = (jj < 31);
    const int  jj_s   = active ? jj : 0;
    const int  j      = jj_s + (jj_s >= i);
    const int  ip     = i - (jj_s < i);

    float4* slabF4 = (float4*)(sAcc + (size_t)i_loc * 384);   // 192 float4 per slab

    // ---- xs loads ----
    float xs[16];
    if (half == 0) {
        // coalesced cooperative load of the contiguous 31x16-float row block
        const float4* g4 = (const float4*)(binp + (((size_t)b * 32 + i) * 31) * 16);
        float4 v0 = g4[lane], v1 = g4[lane + 32], v2 = g4[lane + 64];
        float4 v3 = (lane < 28) ? g4[lane + 96] : make_float4(0.f, 0.f, 0.f, 0.f);
        slabF4[lane]      = v0;
        slabF4[lane + 32] = v1;
        slabF4[lane + 64] = v2;
        if (lane < 28) slabF4[lane + 96] = v3;
        __syncwarp();
        float4 r[4];
#pragma unroll
        for (int q = 0; q < 4; q++) r[q] = slabF4[jj_s * 4 + q];
        __syncwarp();   // all reads done before slab reuse
#pragma unroll
        for (int q = 0; q < 4; q++) {
            xs[4 * q + 0] = r[q].x; xs[4 * q + 1] = r[q].y;
            xs[4 * q + 2] = r[q].z; xs[4 * q + 3] = r[q].w;
        }
    } else {
        // scattered per-lane rows (column access; no coalescing possible)
        const float4* p = (const float4*)(binp + (((size_t)b * 32 + j) * 31 + ip) * 16);
        float4 v[4];
#pragma unroll
        for (int q = 0; q < 4; q++) v[q] = p[q];
#pragma unroll
        for (int q = 0; q < 4; q++) {
            xs[4 * q + 0] = v[q].x; xs[4 * q + 1] = v[q].y;
            xs[4 * q + 2] = v[q].z; xs[4 * q + 3] = v[q].w;
        }
    }
    const float uk = (half == 0) ? una[(size_t)b * 1024 + i * 32 + lane] : 0.0f;

    // ---- prologue: pure loads into shared ----
    {
        const float4* gbw = (const float4*)g_BW;
        sBW[t]       = gbw[t];
        sBW[t + 128] = gbw[t + 128];
    }
    if (t < 128) sBW[t + 256] = ((const float4*)g_BW)[t + 256];
    {
#pragma unroll
        for (int q = 0; q < 3; q++) {
            int idx = t + q * 256;         // 0..767 = j*24 + rd
            int jx = idx / 24, rd = idx - jx * 24;
            sU2[jx * 25 + rd] = g_U2T[b * 768 + idx];
        }
    }
    if (t < 96) {
        int il = t / 24, rd = t - (t / 24) * 24;
        sPU1[il * 24 + rd] = g_PU1T[b * 768 + (ig * 4 + il) * 24 + rd];
    }
    __syncthreads();

    // ---- main loop: 16 kk per half ----
    u64 acc[12];
    if (half == 0) {
#pragma unroll
        for (int rdp = 0; rdp < 12; rdp++) {
            float lo = sPU1[i_loc * 24 + 2 * rdp]     * sU2[j * 25 + 2 * rdp];
            float hi = sPU1[i_loc * 24 + 2 * rdp + 1] * sU2[j * 25 + 2 * rdp + 1];
            acc[rdp] = pk2(lo, hi);
        }
    } else {
        u64 one = pk2(1.0f, 1.0f);
#pragma unroll
        for (int rdp = 0; rdp < 12; rdp++) acc[rdp] = one;
    }

    const uint32_t sb = smem_u32(sBW) + (uint32_t)(half * 16 * 12 * 16);
#pragma unroll
    for (int kl = 0; kl < 16; kl++) {
        u64 xx = pk2(xs[kl], xs[kl]);
#pragma unroll
        for (int rdp = 0; rdp < 12; rdp++) {
            u64 w, c;
            lds_wc(w, c, sb + (uint32_t)((kl * 12 + rdp) * 16));
            acc[rdp] = mul2(acc[rdp], fma2(xx, w, c));
        }
    }

    // ---- exchange: half1 -> its slab ----
    if (half == 1) {
        u64* dst = sAcc + (size_t)i_loc * 384 + (size_t)jj * 12;
#pragma unroll
        for (int rdp = 0; rdp < 12; rdp++) dst[rdp] = acc[rdp];
    }
    __syncthreads();

    if (half == 0) {
        const u64* src = sAcc + (size_t)i_loc * 384 + (size_t)jj * 12;
        float tv[24];
#pragma unroll
        for (int rdp = 0; rdp < 12; rdp++) {
            u64 mm = mul2(acc[rdp], src[rdp]);
            float lo, hi;
            upk2(mm, lo, hi);
            tv[2 * rdp]     = 1.0f - lo;
            tv[2 * rdp + 1] = 1.0f - hi;
        }
        float pr0 = 1.0f, pr1 = 1.0f, pr2 = 1.0f;
#pragma unroll
        for (int d = 0; d < 8; d++) {
            pr0 *= tv[d];
            pr1 *= tv[8 + d];
            pr2 *= tv[16 + d];
        }

        // ---- binary output rows: stage into own slab, then coalesced STG ----
        __syncwarp();   // all src reads in this warp complete before overwrite
        if (active) {
            float4 o[4];
#pragma unroll
            for (int q = 0; q < 4; q++) {
                o[q].x = xs[4 * q + 0]; o[q].y = xs[4 * q + 1];
                o[q].z = xs[4 * q + 2]; o[q].w = xs[4 * q + 3];
            }
            o[3].w = 1.0f - (1.0f - xs[15]) * pr2;
#pragma unroll
            for (int q = 0; q < 4; q++) slabF4[jj * 4 + q] = o[q];
        } else {
            pr0 = 1.0f;
            pr1 = 1.0f;
        }
        __syncwarp();
        {
            float4* outF4 = (float4*)(out + (size_t)b * 16912 + 1040 + (size_t)i * 496);
            outF4[lane]      = slabF4[lane];
            outF4[lane + 32] = slabF4[lane + 32];
            outF4[lane + 64] = slabF4[lane + 64];
            if (lane < 28) outF4[lane + 96] = slabF4[lane + 96];
        }

        // warp product-reductions over jj
        float r0 = pr0, r1 = pr1;
#pragma unroll
        for (int s = 16; s > 0; s >>= 1) {
            r0 *= __shfl_xor_sync(0xFFFFFFFFu, r0, s);
            r1 *= __shfl_xor_sync(0xFFFFFFFFu, r1, s);
        }

        float uv = (lane < 31) ? uk : (1.0f - (1.0f - uk) * r1);
        out[(size_t)b * 16912 + 16 + i * 32 + lane] = uv;

        if (lane == 0) sWarpR0[i_loc] = r0;
    }
    __syncthreads();

    // ---- last-block nullary epilogue (256 blocks -> ticket 255) ----
    if (t == 0) {
        float p = sWarpR0[0] * sWarpR0[1] * sWarpR0[2] * sWarpR0[3];
        __stcg(&g_partB[b * 8 + ig], p);
        __threadfence();
        unsigned int ticket = atomicAdd(&g_ctr, 1u);
        sIsLast = (ticket == 255u) ? 1 : 0;
    }
    __syncthreads();

    if (sIsLast) {
        __threadfence();
        for (int item = t; item < 512; item += 256) {
            int bb = item >> 4, c = item & 15;
            float v = nul[bb * 16 + c];
            if (c == 15) {
                float p = 1.0f;
#pragma unroll
                for (int g = 0; g < 8; g++) p *= __ldcg(&g_partB[bb * 8 + g]);
                v = 1.0f - (1.0f - v) * p;
            }
            out[(size_t)bb * 16912 + c] = v;
        }
        if (t == 0) atomicExch(&g_ctr, 0u);
    }
}

// ============================================================================
extern "C" void kernel_launch(void* const* d_in, const int* in_sizes, int n_in,
                              void* d_out, int out_size) {
    // Identify the 5 inputs by rank order of element count (all distinct):
    //   ork (24) < nul (512) < andk (8064) < una (32768) < binp (507904)
    int order[5] = {0, 1, 2, 3, 4};
    for (int a = 1; a < 5 && a < n_in; a++) {
        int key = order[a];
        int ks = in_sizes[key];
        int bpos = a - 1;
        while (bpos >= 0 && in_sizes[order[bpos]] > ks) {
            order[bpos + 1] = order[bpos];
            bpos--;
        }
        order[bpos + 1] = key;
    }
    const float* ork  = (const float*)d_in[order[0]];
    const float* nul  = (const float*)d_in[order[1]];
    const float* andk = (const float*)d_in[order[2]];
    const float* una  = (const float*)d_in[order[3]];
    const float* binp = (const float*)d_in[order[4]];
    float* out = (float*)d_out;

    k1<<<dim3(32, 2), 384>>>(nul, una, andk, ork);
    k2<<<dim3(8, 32), 256>>>(nul, una, binp, out);
}

// round 13
// speedup vs baseline: 1.1699x; 1.1699x over previous
#include <cuda_runtime.h>
#include <cstdint>

// Problem constants:
// B=32, N=32, P0=16, P1=32, P2=16, R=3, D=8, V=2
// num_in = 112, RD = 24
// out per b: 16 (null) + 1024 (unary) + 32*31*16 (binary) = 16912
// This kernel: grid (3 rules, 32 b) x 1024 threads; block = one rule, all pairs.

#define NUMIN 112

typedef unsigned long long u64;

// -------- packed f32x2 helpers (Blackwell) --------
__device__ __forceinline__ u64 pk2(float a, float b) {
    u64 r; asm("mov.b64 %0, {%1,%2};" : "=l"(r) : "f"(a), "f"(b)); return r;
}
__device__ __forceinline__ void upk2(u64 v, float& a, float& b) {
    asm("mov.b64 {%0,%1}, %2;" : "=f"(a), "=f"(b) : "l"(v));
}
__device__ __forceinline__ u64 fma2(u64 a, u64 b, u64 c) {
    u64 d; asm("fma.rn.f32x2 %0, %1, %2, %3;" : "=l"(d) : "l"(a), "l"(b), "l"(c)); return d;
}
__device__ __forceinline__ u64 mul2(u64 a, u64 b) {
    u64 d; asm("mul.rn.f32x2 %0, %1, %2;" : "=l"(d) : "l"(a), "l"(b)); return d;
}
__device__ __forceinline__ void lds_wc(u64& w, u64& c, uint32_t addr) {
    asm volatile("ld.shared.v2.u64 {%0,%1}, [%2];" : "=l"(w), "=l"(c) : "r"(addr));
}
__device__ __forceinline__ uint32_t smem_u32(const void* p) {
    uint32_t a;
    asm("{ .reg .u64 t; cvta.to.shared.u64 t, %1; cvt.u32.u64 %0, t; }" : "=r"(a) : "l"(p));
    return a;
}

// ============================================================================
// Fused per-rule kernel. grid = (3 r, 32 b), block = 1024 (i = t>>5, jj = lane).
// Block (r,b): softmax for its 8 rds only; U2/PU1 for its rds; main loop over
// 32 kk x 4 rdp; writes the outputs its rule owns. No cross-block sync at all.
// ============================================================================
__global__ __launch_bounds__(1024, 1)
void kRule(const float* __restrict__ nul, const float* __restrict__ una,
           const float* __restrict__ binp, const float* __restrict__ andk,
           const float* __restrict__ ork, float* __restrict__ out) {
    __shared__ float2 sWC[8 * NUMIN];    // (w,c) for local rds lr=0..7
    __shared__ float  sU[32 * 33];       // unary transposed [k][i], stride 33
    __shared__ float4 sBW[32 * 4];       // packed binary weights [kk][q]
    __shared__ float  sU2[32 * 9];       // U2[j][lr], stride 9
    __shared__ float  sPU1[32 * 8];      // PU1[i][lr]
    __shared__ float  sN[16];
    __shared__ float  sOK[8];
    __shared__ float  sW0[32];           // per-warp nullary partials (r==0)

    const int r  = blockIdx.x;           // rule 0..2
    const int b  = blockIdx.y;           // 0..31
    const int t  = threadIdx.x;          // 0..1023
    const int i  = t >> 5;
    const int lane = t & 31;

    const int  jj     = lane;
    const bool active = (jj < 31);
    const int  jj_s   = active ? jj : 0;
    const int  j      = jj_s + (jj_s >= i);   // second object
    const int  ip     = i - (jj_s < i);       // column of (j,i) row

    // ---- hoisted xs loads (overlap phase-1 latency) ----
    float xs1[16], xs2[16];
    {
        const float4* p1 = (const float4*)(binp + (((size_t)b * 32 + i) * 31 + jj_s) * 16);
        const float4* p2 = (const float4*)(binp + (((size_t)b * 32 + j) * 31 + ip)  * 16);
        float4 va[4], vb[4];
#pragma unroll
        for (int q = 0; q < 4; q++) va[q] = p1[q];
#pragma unroll
        for (int q = 0; q < 4; q++) vb[q] = p2[q];
#pragma unroll
        for (int q = 0; q < 4; q++) {
            xs1[4 * q + 0] = va[q].x; xs1[4 * q + 1] = va[q].y;
            xs1[4 * q + 2] = va[q].z; xs1[4 * q + 3] = va[q].w;
            xs2[4 * q + 0] = vb[q].x; xs2[4 * q + 1] = vb[q].y;
            xs2[4 * q + 2] = vb[q].z; xs2[4 * q + 3] = vb[q].w;
        }
    }
    const float uk = (r == 1) ? una[(size_t)b * 1024 + i * 32 + lane] : 0.0f;

    // ---- phase 1: local softmax (896 triples), staging ----
    if (t < 896) {
        int lr = t / NUMIN, k = t - lr * NUMIN;
        const float* p = andk + ((size_t)((r * 8 + lr) * NUMIN + k)) * 3;
        float a0 = __ldg(p), a1 = __ldg(p + 1), a2 = __ldg(p + 2);
        // 2-exp softmax: divide by e2
        float r0 = __expf(a0 - a2), r1 = __expf(a1 - a2);
        float inv = __fdividef(1.0f, r0 + r1 + 1.0f);
        sWC[lr * NUMIN + k] = make_float2((r0 - r1) * inv, (r1 + 1.0f) * inv);
    } else if (t < 912) {
        sN[t - 896] = nul[b * 16 + (t - 896)];
    } else if (t < 920) {
        float x = ork[r * 8 + (t - 912)];
        sOK[t - 912] = __fdividef(1.0f, 1.0f + __expf(-x));
    }
    {
        int ii = t >> 5, k = t & 31;
        sU[k * 33 + ii] = una[b * 1024 + t];
    }
    __syncthreads();   // bar1

    // ---- phase 2: U2 (256), PU1 (256), sBW (128) ----
    if (t < 256) {
        int jx = t & 31, lr = t >> 5;
        const float2* wc = sWC + lr * NUMIN + 48;
        float pa = 1.0f, pb = 1.0f, pc = 1.0f, pd = 1.0f;
#pragma unroll
        for (int k = 0; k < 8; k++) {
            float2 w0 = wc[k],      w1 = wc[8 + k];
            float2 w2 = wc[16 + k], w3 = wc[24 + k];
            pa *= fmaf(sU[k * 33 + jx],        w0.x, w0.y);
            pb *= fmaf(sU[(8 + k) * 33 + jx],  w1.x, w1.y);
            pc *= fmaf(sU[(16 + k) * 33 + jx], w2.x, w2.y);
            pd *= fmaf(sU[(24 + k) * 33 + jx], w3.x, w3.y);
        }
        sU2[jx * 9 + lr] = (pa * pb) * (pc * pd);
    } else if (t < 512) {
        int tid = t - 256;
        int ii = tid & 31, lr = tid >> 5;
        const float2* wc = sWC + lr * NUMIN;
        float pa = 1.0f, pb = 1.0f, pc = 1.0f, pd = 1.0f;
#pragma unroll
        for (int k = 0; k < 8; k++) {
            float2 w0 = wc[k], w1 = wc[8 + k];
            pa *= fmaf(sN[k],     w0.x, w0.y);
            pb *= fmaf(sN[8 + k], w1.x, w1.y);
        }
#pragma unroll
        for (int k = 0; k < 16; k++) {
            float2 w0 = wc[16 + k], w1 = wc[32 + k];
            pc *= fmaf(sU[k * 33 + ii],        w0.x, w0.y);
            pd *= fmaf(sU[(16 + k) * 33 + ii], w1.x, w1.y);
        }
        sPU1[ii * 8 + lr] = ((pa * pb) * (pc * pd)) * sOK[lr];
    } else if (t < 640) {
        int idx = t - 512;                  // 0..127
        int kk = idx >> 2, q = idx & 3;
        int slice = (kk < 16) ? (80 + kk) : (96 + kk - 16);
        float2 lo = sWC[(2 * q)     * NUMIN + slice];
        float2 hi = sWC[(2 * q + 1) * NUMIN + slice];
        sBW[kk * 4 + q] = make_float4(lo.x, hi.x, lo.y, hi.y);
    }
    __syncthreads();   // bar2

    // ---- main loop: 32 kk x 4 rdp ----
    u64 acc[4];
#pragma unroll
    for (int q = 0; q < 4; q++) {
        float lo = sPU1[i * 8 + 2 * q]     * sU2[j * 9 + 2 * q];
        float hi = sPU1[i * 8 + 2 * q + 1] * sU2[j * 9 + 2 * q + 1];
        acc[q] = pk2(lo, hi);
    }

    const uint32_t sb = smem_u32(sBW);
#pragma unroll
    for (int kk = 0; kk < 32; kk++) {
        float x = (kk < 16) ? xs1[kk] : xs2[kk - 16];
        u64 xx = pk2(x, x);
#pragma unroll
        for (int q = 0; q < 4; q++) {
            u64 w, c;
            lds_wc(w, c, sb + (uint32_t)((kk * 4 + q) * 16));
            acc[q] = mul2(acc[q], fma2(xx, w, c));
        }
    }

    // ---- per-rule disjunct product over D=8 ----
    float tv[8];
#pragma unroll
    for (int q = 0; q < 4; q++) {
        float lo, hi;
        upk2(acc[q], lo, hi);
        tv[2 * q]     = 1.0f - lo;
        tv[2 * q + 1] = 1.0f - hi;
    }
    float pr = ((tv[0] * tv[1]) * (tv[2] * tv[3])) * ((tv[4] * tv[5]) * (tv[6] * tv[7]));

    // ---- rule-specific outputs ----
    if (r == 2) {
        // binary rows: channels 0..14 copy, channel 15 merged
        if (active) {
            float4 o[4];
#pragma unroll
            for (int q = 0; q < 4; q++) {
                o[q].x = xs1[4 * q + 0]; o[q].y = xs1[4 * q + 1];
                o[q].z = xs1[4 * q + 2]; o[q].w = xs1[4 * q + 3];
            }
            o[3].w = 1.0f - (1.0f - xs1[15]) * pr;
            float4* ob = (float4*)(out + (size_t)b * 16912 + 1040 + (size_t)(i * 31 + jj) * 16);
#pragma unroll
            for (int q = 0; q < 4; q++) ob[q] = o[q];
        }
    } else if (r == 1) {
        // unary rows: reduce pr over jj within the warp
        float rp = active ? pr : 1.0f;
#pragma unroll
        for (int s = 16; s > 0; s >>= 1)
            rp *= __shfl_xor_sync(0xFFFFFFFFu, rp, s);
        float uv = (lane < 31) ? uk : (1.0f - (1.0f - uk) * rp);
        out[(size_t)b * 16912 + 16 + i * 32 + lane] = uv;
    } else {
        // nullary: full in-block product over (i, jj)
        float rp = active ? pr : 1.0f;
#pragma unroll
        for (int s = 16; s > 0; s >>= 1)
            rp *= __shfl_xor_sync(0xFFFFFFFFu, rp, s);
        if (lane == 0) sW0[i] = rp;
        __syncthreads();
        if (t < 15) {
            out[(size_t)b * 16912 + t] = sN[t];
        }
        if (t < 32 && t >= 0 && (t >> 5) == 0) {
            // warp 0: product of 32 warp partials
            float p = sW0[lane];
#pragma unroll
            for (int s = 16; s > 0; s >>= 1)
                p *= __shfl_xor_sync(0xFFFFFFFFu, p, s);
            if (lane == 0)
                out[(size_t)b * 16912 + 15] = 1.0f - (1.0f - sN[15]) * p;
        }
    }
}

// ============================================================================
extern "C" void kernel_launch(void* const* d_in, const int* in_sizes, int n_in,
                              void* d_out, int out_size) {
    // Identify the 5 inputs by rank order of element count (all distinct):
    //   ork (24) < nul (512) < andk (8064) < una (32768) < binp (507904)
    int order[5] = {0, 1, 2, 3, 4};
    for (int a = 1; a < 5 && a < n_in; a++) {
        int key = order[a];
        int ks = in_sizes[key];
        int bpos = a - 1;
        while (bpos >= 0 && in_sizes[order[bpos]] > ks) {
            order[bpos + 1] = order[bpos];
            bpos--;
        }
        order[bpos + 1] = key;
    }
    const float* ork  = (const float*)d_in[order[0]];
    const float* nul  = (const float*)d_in[order[1]];
    const float* andk = (const float*)d_in[order[2]];
    const float* una  = (const float*)d_in[order[3]];
    const float* binp = (const float*)d_in[order[4]];
    float* out = (float*)d_out;

    kRule<<<dim3(3, 32), 1024>>>(nul, una, binp, andk, ork, out);
}

// round 14
// speedup vs baseline: 1.1875x; 1.0151x over previous
#include <cuda_runtime.h>
#include <cstdint>

// Problem constants:
// B=32, N=32, P0=16, P1=32, P2=16, R=3, D=8, V=2
// num_in = 112, RD = 24
// out per b: 16 (null) + 1024 (unary) + 32*31*16 (binary) = 16912
// This kernel: grid (3 rules, 32 b) x 1024 threads; block = one rule, all pairs.

#define NUMIN 112

typedef unsigned long long u64;

// -------- packed f32x2 helpers (Blackwell) --------
__device__ __forceinline__ u64 pk2(float a, float b) {
    u64 r; asm("mov.b64 %0, {%1,%2};" : "=l"(r) : "f"(a), "f"(b)); return r;
}
__device__ __forceinline__ void upk2(u64 v, float& a, float& b) {
    asm("mov.b64 {%0,%1}, %2;" : "=f"(a), "=f"(b) : "l"(v));
}
__device__ __forceinline__ u64 fma2(u64 a, u64 b, u64 c) {
    u64 d; asm("fma.rn.f32x2 %0, %1, %2, %3;" : "=l"(d) : "l"(a), "l"(b), "l"(c)); return d;
}
__device__ __forceinline__ u64 mul2(u64 a, u64 b) {
    u64 d; asm("mul.rn.f32x2 %0, %1, %2;" : "=l"(d) : "l"(a), "l"(b)); return d;
}
__device__ __forceinline__ void lds_wc(u64& w, u64& c, uint32_t addr) {
    asm volatile("ld.shared.v2.u64 {%0,%1}, [%2];" : "=l"(w), "=l"(c) : "r"(addr));
}
__device__ __forceinline__ uint32_t smem_u32(const void* p) {
    uint32_t a;
    asm("{ .reg .u64 t; cvta.to.shared.u64 t, %1; cvt.u32.u64 %0, t; }" : "=r"(a) : "l"(p));
    return a;
}

// ============================================================================
// Fused per-rule kernel. grid = (3 r, 32 b), block = 1024 (i = t>>5, jj = lane).
// Block (r,b): softmax for its 8 rds only; U2/PU1 for its rds; main loop over
// 32 kk x 4 rdp; writes the outputs its rule owns. No cross-block sync at all.
// ============================================================================
__global__ __launch_bounds__(1024, 1)
void kRule(const float* __restrict__ nul, const float* __restrict__ una,
           const float* __restrict__ binp, const float* __restrict__ andk,
           const float* __restrict__ ork, float* __restrict__ out) {
    __shared__ float2 sWC[8 * NUMIN];    // (w,c) for local rds lr=0..7
    __shared__ float  sU[32 * 33];       // unary transposed [k][i], stride 33
    __shared__ float4 sBW[32 * 4];       // packed binary weights [kk][q]
    __shared__ float  sU2[32 * 9];       // U2[j][lr], stride 9
    __shared__ float  sPU1[32 * 8];      // PU1[i][lr]
    __shared__ float  sN[16];
    __shared__ float  sOK[8];
    __shared__ float  sW0[32];           // per-warp nullary partials (r==0)

    const int r  = blockIdx.x;           // rule 0..2
    const int b  = blockIdx.y;           // 0..31
    const int t  = threadIdx.x;          // 0..1023
    const int i  = t >> 5;
    const int lane = t & 31;

    const int  jj     = lane;
    const bool active = (jj < 31);
    const int  jj_s   = active ? jj : 0;
    const int  j      = jj_s + (jj_s >= i);   // second object
    const int  ip     = i - (jj_s < i);       // column of (j,i) row

    // ---- hoisted xs loads (overlap phase-1 latency) ----
    float xs1[16], xs2[16];
    {
        const float4* p1 = (const float4*)(binp + (((size_t)b * 32 + i) * 31 + jj_s) * 16);
        const float4* p2 = (const float4*)(binp + (((size_t)b * 32 + j) * 31 + ip)  * 16);
        float4 va[4], vb[4];
#pragma unroll
        for (int q = 0; q < 4; q++) va[q] = p1[q];
#pragma unroll
        for (int q = 0; q < 4; q++) vb[q] = p2[q];
#pragma unroll
        for (int q = 0; q < 4; q++) {
            xs1[4 * q + 0] = va[q].x; xs1[4 * q + 1] = va[q].y;
            xs1[4 * q + 2] = va[q].z; xs1[4 * q + 3] = va[q].w;
            xs2[4 * q + 0] = vb[q].x; xs2[4 * q + 1] = vb[q].y;
            xs2[4 * q + 2] = vb[q].z; xs2[4 * q + 3] = vb[q].w;
        }
    }
    const float uk = (r == 1) ? una[(size_t)b * 1024 + i * 32 + lane] : 0.0f;

    // ---- phase 1: local softmax (896 triples), staging ----
    if (t < 896) {
        int lr = t / NUMIN, k = t - lr * NUMIN;
        const float* p = andk + ((size_t)((r * 8 + lr) * NUMIN + k)) * 3;
        float a0 = __ldg(p), a1 = __ldg(p + 1), a2 = __ldg(p + 2);
        // 2-exp softmax: divide by e2
        float r0 = __expf(a0 - a2), r1 = __expf(a1 - a2);
        float inv = __fdividef(1.0f, r0 + r1 + 1.0f);
        sWC[lr * NUMIN + k] = make_float2((r0 - r1) * inv, (r1 + 1.0f) * inv);
    } else if (t < 912) {
        sN[t - 896] = nul[b * 16 + (t - 896)];
    } else if (t < 920) {
        float x = ork[r * 8 + (t - 912)];
        sOK[t - 912] = __fdividef(1.0f, 1.0f + __expf(-x));
    }
    {
        int ii = t >> 5, k = t & 31;
        sU[k * 33 + ii] = una[b * 1024 + t];
    }
    __syncthreads();   // bar1

    // ---- phase 2: U2 (256), PU1 (256), sBW (128) ----
    if (t < 256) {
        int jx = t & 31, lr = t >> 5;
        const float2* wc = sWC + lr * NUMIN + 48;
        float pa = 1.0f, pb = 1.0f, pc = 1.0f, pd = 1.0f;
#pragma unroll
        for (int k = 0; k < 8; k++) {
            float2 w0 = wc[k],      w1 = wc[8 + k];
            float2 w2 = wc[16 + k], w3 = wc[24 + k];
            pa *= fmaf(sU[k * 33 + jx],        w0.x, w0.y);
            pb *= fmaf(sU[(8 + k) * 33 + jx],  w1.x, w1.y);
            pc *= fmaf(sU[(16 + k) * 33 + jx], w2.x, w2.y);
            pd *= fmaf(sU[(24 + k) * 33 + jx], w3.x, w3.y);
        }
        sU2[jx * 9 + lr] = (pa * pb) * (pc * pd);
    } else if (t < 512) {
        int tid = t - 256;
        int ii = tid & 31, lr = tid >> 5;
        const float2* wc = sWC + lr * NUMIN;
        float pa = 1.0f, pb = 1.0f, pc = 1.0f, pd = 1.0f;
#pragma unroll
        for (int k = 0; k < 8; k++) {
            float2 w0 = wc[k], w1 = wc[8 + k];
            pa *= fmaf(sN[k],     w0.x, w0.y);
            pb *= fmaf(sN[8 + k], w1.x, w1.y);
        }
#pragma unroll
        for (int k = 0; k < 16; k++) {
            float2 w0 = wc[16 + k], w1 = wc[32 + k];
            pc *= fmaf(sU[k * 33 + ii],        w0.x, w0.y);
            pd *= fmaf(sU[(16 + k) * 33 + ii], w1.x, w1.y);
        }
        sPU1[ii * 8 + lr] = ((pa * pb) * (pc * pd)) * sOK[lr];
    } else if (t < 640) {
        int idx = t - 512;                  // 0..127
        int kk = idx >> 2, q = idx & 3;
        int slice = (kk < 16) ? (80 + kk) : (96 + kk - 16);
        float2 lo = sWC[(2 * q)     * NUMIN + slice];
        float2 hi = sWC[(2 * q + 1) * NUMIN + slice];
        sBW[kk * 4 + q] = make_float4(lo.x, hi.x, lo.y, hi.y);
    }
    __syncthreads();   // bar2

    // ---- main loop: 32 kk x 4 rdp ----
    u64 acc[4];
#pragma unroll
    for (int q = 0; q < 4; q++) {
        float lo = sPU1[i * 8 + 2 * q]     * sU2[j * 9 + 2 * q];
        float hi = sPU1[i * 8 + 2 * q + 1] * sU2[j * 9 + 2 * q + 1];
        acc[q] = pk2(lo, hi);
    }

    const uint32_t sb = smem_u32(sBW);
#pragma unroll
    for (int kk = 0; kk < 32; kk++) {
        float x = (kk < 16) ? xs1[kk] : xs2[kk - 16];
        u64 xx = pk2(x, x);
#pragma unroll
        for (int q = 0; q < 4; q++) {
            u64 w, c;
            lds_wc(w, c, sb + (uint32_t)((kk * 4 + q) * 16));
            acc[q] = mul2(acc[q], fma2(xx, w, c));
        }
    }

    // ---- per-rule disjunct product over D=8 ----
    float tv[8];
#pragma unroll
    for (int q = 0; q < 4; q++) {
        float lo, hi;
        upk2(acc[q], lo, hi);
        tv[2 * q]     = 1.0f - lo;
        tv[2 * q + 1] = 1.0f - hi;
    }
    float pr = ((tv[0] * tv[1]) * (tv[2] * tv[3])) * ((tv[4] * tv[5]) * (tv[6] * tv[7]));

    // ---- rule-specific outputs ----
    if (r == 2) {
        // binary rows: channels 0..14 copy, channel 15 merged
        if (active) {
            float4 o[4];
#pragma unroll
            for (int q = 0; q < 4; q++) {
                o[q].x = xs1[4 * q + 0]; o[q].y = xs1[4 * q + 1];
                o[q].z = xs1[4 * q + 2]; o[q].w = xs1[4 * q + 3];
            }
            o[3].w = 1.0f - (1.0f - xs1[15]) * pr;
            float4* ob = (float4*)(out + (size_t)b * 16912 + 1040 + (size_t)(i * 31 + jj) * 16);
#pragma unroll
            for (int q = 0; q < 4; q++) ob[q] = o[q];
        }
    } else if (r == 1) {
        // unary rows: reduce pr over jj within the warp
        float rp = active ? pr : 1.0f;
#pragma unroll
        for (int s = 16; s > 0; s >>= 1)
            rp *= __shfl_xor_sync(0xFFFFFFFFu, rp, s);
        float uv = (lane < 31) ? uk : (1.0f - (1.0f - uk) * rp);
        out[(size_t)b * 16912 + 16 + i * 32 + lane] = uv;
    } else {
        // nullary: full in-block product over (i, jj)
        float rp = active ? pr : 1.0f;
#pragma unroll
        for (int s = 16; s > 0; s >>= 1)
            rp *= __shfl_xor_sync(0xFFFFFFFFu, rp, s);
        if (lane == 0) sW0[i] = rp;
        __syncthreads();
        if (t < 15) {
            out[(size_t)b * 16912 + t] = sN[t];
        }
        if (t < 32 && t >= 0 && (t >> 5) == 0) {
            // warp 0: product of 32 warp partials
            float p = sW0[lane];
#pragma unroll
            for (int s = 16; s > 0; s >>= 1)
                p *= __shfl_xor_sync(0xFFFFFFFFu, p, s);
            if (lane == 0)
                out[(size_t)b * 16912 + 15] = 1.0f - (1.0f - sN[15]) * p;
        }
    }
}

// ============================================================================
extern "C" void kernel_launch(void* const* d_in, const int* in_sizes, int n_in,
                              void* d_out, int out_size) {
    // Identify the 5 inputs by rank order of element count (all distinct):
    //   ork (24) < nul (512) < andk (8064) < una (32768) < binp (507904)
    int order[5] = {0, 1, 2, 3, 4};
    for (int a = 1; a < 5 && a < n_in; a++) {
        int key = order[a];
        int ks = in_sizes[key];
        int bpos = a - 1;
        while (bpos >= 0 && in_sizes[order[bpos]] > ks) {
            order[bpos + 1] = order[bpos];
            bpos--;
        }
        order[bpos + 1] = key;
    }
    const float* ork  = (const float*)d_in[order[0]];
    const float* nul  = (const float*)d_in[order[1]];
    const float* andk = (const float*)d_in[order[2]];
    const float* una  = (const float*)d_in[order[3]];
    const float* binp = (const float*)d_in[order[4]];
    float* out = (float*)d_out;

    kRule<<<dim3(3, 32), 1024>>>(nul, una, binp, andk, ork, out);
}

// round 15
// speedup vs baseline: 1.1901x; 1.0022x over previous
#include <cuda_runtime.h>
#include <cstdint>

// Problem constants:
// B=32, N=32, P0=16, P1=32, P2=16, R=3, D=8, V=2
// num_in = 112, RD = 24
// out per b: 16 (null) + 1024 (unary) + 32*31*16 (binary) = 16912
// This kernel: grid (3 rules, 32 b) x 1024 threads; block = one rule, all pairs.

#define NUMIN 112

typedef unsigned long long u64;

// -------- packed f32x2 helpers (Blackwell) --------
__device__ __forceinline__ u64 pk2(float a, float b) {
    u64 r; asm("mov.b64 %0, {%1,%2};" : "=l"(r) : "f"(a), "f"(b)); return r;
}
__device__ __forceinline__ void upk2(u64 v, float& a, float& b) {
    asm("mov.b64 {%0,%1}, %2;" : "=f"(a), "=f"(b) : "l"(v));
}
__device__ __forceinline__ u64 fma2(u64 a, u64 b, u64 c) {
    u64 d; asm("fma.rn.f32x2 %0, %1, %2, %3;" : "=l"(d) : "l"(a), "l"(b), "l"(c)); return d;
}
__device__ __forceinline__ u64 mul2(u64 a, u64 b) {
    u64 d; asm("mul.rn.f32x2 %0, %1, %2;" : "=l"(d) : "l"(a), "l"(b)); return d;
}
__device__ __forceinline__ void lds_wc(u64& w, u64& c, uint32_t addr) {
    asm volatile("ld.shared.v2.u64 {%0,%1}, [%2];" : "=l"(w), "=l"(c) : "r"(addr));
}
__device__ __forceinline__ uint32_t smem_u32(const void* p) {
    uint32_t a;
    asm("{ .reg .u64 t; cvta.to.shared.u64 t, %1; cvt.u32.u64 %0, t; }" : "=r"(a) : "l"(p));
    return a;
}

// ============================================================================
// Fused per-rule kernel. grid = (3 r, 32 b), block = 1024 (i = t>>5, jj = lane).
// Block (r,b): softmax for its 8 rds only; U2/PU1 for its rds; main loop over
// 32 kk x 4 rdp; writes the outputs its rule owns. No cross-block sync at all.
// ============================================================================
__global__ __launch_bounds__(1024, 1)
void kRule(const float* __restrict__ nul, const float* __restrict__ una,
           const float* __restrict__ binp, const float* __restrict__ andk,
           const float* __restrict__ ork, float* __restrict__ out) {
    __shared__ float2 sWC[8 * NUMIN];    // (w,c) for local rds lr=0..7
    __shared__ float  sU[32 * 33];       // unary transposed [k][i], stride 33
    __shared__ float4 sBW[32 * 4];       // packed binary weights [kk][q]
    __shared__ float  sU2[32 * 9];       // U2[j][lr], stride 9
    __shared__ float  sPU1[32 * 8];      // PU1[i][lr]
    __shared__ float  sN[16];
    __shared__ float  sOK[8];
    __shared__ float  sW0[32];           // per-warp nullary partials (r==0)

    const int r  = blockIdx.x;           // rule 0..2
    const int b  = blockIdx.y;           // 0..31
    const int t  = threadIdx.x;          // 0..1023
    const int i  = t >> 5;
    const int lane = t & 31;

    const int  jj     = lane;
    const bool active = (jj < 31);
    const int  jj_s   = active ? jj : 0;
    const int  j      = jj_s + (jj_s >= i);   // second object
    const int  ip     = i - (jj_s < i);       // column of (j,i) row

    // ---- hoisted xs loads (overlap phase-1 latency) ----
    float xs1[16], xs2[16];
    {
        const float4* p1 = (const float4*)(binp + (((size_t)b * 32 + i) * 31 + jj_s) * 16);
        const float4* p2 = (const float4*)(binp + (((size_t)b * 32 + j) * 31 + ip)  * 16);
        float4 va[4], vb[4];
#pragma unroll
        for (int q = 0; q < 4; q++) va[q] = p1[q];
#pragma unroll
        for (int q = 0; q < 4; q++) vb[q] = p2[q];
#pragma unroll
        for (int q = 0; q < 4; q++) {
            xs1[4 * q + 0] = va[q].x; xs1[4 * q + 1] = va[q].y;
            xs1[4 * q + 2] = va[q].z; xs1[4 * q + 3] = va[q].w;
            xs2[4 * q + 0] = vb[q].x; xs2[4 * q + 1] = vb[q].y;
            xs2[4 * q + 2] = vb[q].z; xs2[4 * q + 3] = vb[q].w;
        }
    }
    const float uk = (r == 1) ? una[(size_t)b * 1024 + i * 32 + lane] : 0.0f;

    // ---- phase 1: local softmax (896 triples), staging ----
    if (t < 896) {
        int lr = t / NUMIN, k = t - lr * NUMIN;
        const float* p = andk + ((size_t)((r * 8 + lr) * NUMIN + k)) * 3;
        float a0 = __ldg(p), a1 = __ldg(p + 1), a2 = __ldg(p + 2);
        // 2-exp softmax: divide by e2
        float r0 = __expf(a0 - a2), r1 = __expf(a1 - a2);
        float inv = __fdividef(1.0f, r0 + r1 + 1.0f);
        sWC[lr * NUMIN + k] = make_float2((r0 - r1) * inv, (r1 + 1.0f) * inv);
    } else if (t < 912) {
        sN[t - 896] = nul[b * 16 + (t - 896)];
    } else if (t < 920) {
        float x = ork[r * 8 + (t - 912)];
        sOK[t - 912] = __fdividef(1.0f, 1.0f + __expf(-x));
    }
    {
        int ii = t >> 5, k = t & 31;
        sU[k * 33 + ii] = una[b * 1024 + t];
    }
    __syncthreads();   // bar1

    // ---- phase 2: U2 (256), PU1 (256), sBW (128) ----
    if (t < 256) {
        int jx = t & 31, lr = t >> 5;
        const float2* wc = sWC + lr * NUMIN + 48;
        float pa = 1.0f, pb = 1.0f, pc = 1.0f, pd = 1.0f;
#pragma unroll
        for (int k = 0; k < 8; k++) {
            float2 w0 = wc[k],      w1 = wc[8 + k];
            float2 w2 = wc[16 + k], w3 = wc[24 + k];
            pa *= fmaf(sU[k * 33 + jx],        w0.x, w0.y);
            pb *= fmaf(sU[(8 + k) * 33 + jx],  w1.x, w1.y);
            pc *= fmaf(sU[(16 + k) * 33 + jx], w2.x, w2.y);
            pd *= fmaf(sU[(24 + k) * 33 + jx], w3.x, w3.y);
        }
        sU2[jx * 9 + lr] = (pa * pb) * (pc * pd);
    } else if (t < 512) {
        int tid = t - 256;
        int ii = tid & 31, lr = tid >> 5;
        const float2* wc = sWC + lr * NUMIN;
        float pa = 1.0f, pb = 1.0f, pc = 1.0f, pd = 1.0f;
#pragma unroll
        for (int k = 0; k < 8; k++) {
            float2 w0 = wc[k], w1 = wc[8 + k];
            pa *= fmaf(sN[k],     w0.x, w0.y);
            pb *= fmaf(sN[8 + k], w1.x, w1.y);
        }
#pragma unroll
        for (int k = 0; k < 16; k++) {
            float2 w0 = wc[16 + k], w1 = wc[32 + k];
            pc *= fmaf(sU[k * 33 + ii],        w0.x, w0.y);
            pd *= fmaf(sU[(16 + k) * 33 + ii], w1.x, w1.y);
        }
        sPU1[ii * 8 + lr] = ((pa * pb) * (pc * pd)) * sOK[lr];
    } else if (t < 640) {
        int idx = t - 512;                  // 0..127
        int kk = idx >> 2, q = idx & 3;
        int slice = (kk < 16) ? (80 + kk) : (96 + kk - 16);
        float2 lo = sWC[(2 * q)     * NUMIN + slice];
        float2 hi = sWC[(2 * q + 1) * NUMIN + slice];
        sBW[kk * 4 + q] = make_float4(lo.x, hi.x, lo.y, hi.y);
    }
    __syncthreads();   // bar2

    // ---- main loop: 32 kk x 4 rdp ----
    u64 acc[4];
#pragma unroll
    for (int q = 0; q < 4; q++) {
        float lo = sPU1[i * 8 + 2 * q]     * sU2[j * 9 + 2 * q];
        float hi = sPU1[i * 8 + 2 * q + 1] * sU2[j * 9 + 2 * q + 1];
        acc[q] = pk2(lo, hi);
    }

    const uint32_t sb = smem_u32(sBW);
#pragma unroll
    for (int kk = 0; kk < 32; kk++) {
        float x = (kk < 16) ? xs1[kk] : xs2[kk - 16];
        u64 xx = pk2(x, x);
#pragma unroll
        for (int q = 0; q < 4; q++) {
            u64 w, c;
            lds_wc(w, c, sb + (uint32_t)((kk * 4 + q) * 16));
            acc[q] = mul2(acc[q], fma2(xx, w, c));
        }
    }

    // ---- per-rule disjunct product over D=8 ----
    float tv[8];
#pragma unroll
    for (int q = 0; q < 4; q++) {
        float lo, hi;
        upk2(acc[q], lo, hi);
        tv[2 * q]     = 1.0f - lo;
        tv[2 * q + 1] = 1.0f - hi;
    }
    float pr = ((tv[0] * tv[1]) * (tv[2] * tv[3])) * ((tv[4] * tv[5]) * (tv[6] * tv[7]));

    // ---- rule-specific outputs ----
    if (r == 2) {
        // binary rows: channels 0..14 copy, channel 15 merged
        if (active) {
            float4 o[4];
#pragma unroll
            for (int q = 0; q < 4; q++) {
                o[q].x = xs1[4 * q + 0]; o[q].y = xs1[4 * q + 1];
                o[q].z = xs1[4 * q + 2]; o[q].w = xs1[4 * q + 3];
            }
            o[3].w = 1.0f - (1.0f - xs1[15]) * pr;
            float4* ob = (float4*)(out + (size_t)b * 16912 + 1040 + (size_t)(i * 31 + jj) * 16);
#pragma unroll
            for (int q = 0; q < 4; q++) ob[q] = o[q];
        }
    } else if (r == 1) {
        // unary rows: reduce pr over jj within the warp
        float rp = active ? pr : 1.0f;
#pragma unroll
        for (int s = 16; s > 0; s >>= 1)
            rp *= __shfl_xor_sync(0xFFFFFFFFu, rp, s);
        float uv = (lane < 31) ? uk : (1.0f - (1.0f - uk) * rp);
        out[(size_t)b * 16912 + 16 + i * 32 + lane] = uv;
    } else {
        // nullary: full in-block product over (i, jj)
        float rp = active ? pr : 1.0f;
#pragma unroll
        for (int s = 16; s > 0; s >>= 1)
            rp *= __shfl_xor_sync(0xFFFFFFFFu, rp, s);
        if (lane == 0) sW0[i] = rp;
        __syncthreads();
        if (t < 15) {
            out[(size_t)b * 16912 + t] = sN[t];
        }
        if (t < 32 && t >= 0 && (t >> 5) == 0) {
            // warp 0: product of 32 warp partials
            float p = sW0[lane];
#pragma unroll
            for (int s = 16; s > 0; s >>= 1)
                p *= __shfl_xor_sync(0xFFFFFFFFu, p, s);
            if (lane == 0)
                out[(size_t)b * 16912 + 15] = 1.0f - (1.0f - sN[15]) * p;
        }
    }
}

// ============================================================================
extern "C" void kernel_launch(void* const* d_in, const int* in_sizes, int n_in,
                              void* d_out, int out_size) {
    // Identify the 5 inputs by rank order of element count (all distinct):
    //   ork (24) < nul (512) < andk (8064) < una (32768) < binp (507904)
    int order[5] = {0, 1, 2, 3, 4};
    for (int a = 1; a < 5 && a < n_in; a++) {
        int key = order[a];
        int ks = in_sizes[key];
        int bpos = a - 1;
        while (bpos >= 0 && in_sizes[order[bpos]] > ks) {
            order[bpos + 1] = order[bpos];
            bpos--;
        }
        order[bpos + 1] = key;
    }
    const float* ork  = (const float*)d_in[order[0]];
    const float* nul  = (const float*)d_in[order[1]];
    const float* andk = (const float*)d_in[order[2]];
    const float* una  = (const float*)d_in[order[3]];
    const float* binp = (const float*)d_in[order[4]];
    float* out = (float*)d_out;

    kRule<<<dim3(3, 32), 1024>>>(nul, una, binp, andk, ork, out);
}